// round 16
// baseline (speedup 1.0000x reference)
#include <cuda_runtime.h>
#include <cuda_fp16.h>

// BatchDotPred: out[e] = dot(feat[src[e]], feat[dst[e]]), D=128.
//
// R13 hit the L1tex wavefront-replay floor: LDG.128 spanning 2 rows = 4
// wavefronts/instr at 2.07 cyc/wf (within-LDG replay) = ~62 B/cyc/SM = 62us.
// R14: single-line gathers. Whole warp per edge, LDG.32 (32 lanes x 4B = one
// 128B line = ONE wavefront at 1.0 cyc/wf cross-LDG rate = 128 B/cyc/SM).
// 4 LDG.32 per edge, 8-edge ILP, 5-step fp32 butterfly reduction.

#define N_NODES_MAX 100000

// fp16 feature table: 100000 rows x 128 halves = 256B/row.
__device__ uint4 g_featH[N_NODES_MAX * 16];

__global__ void __launch_bounds__(256) convert_k(const float4* __restrict__ feat, int n8)
{
    int i = blockIdx.x * blockDim.x + threadIdx.x;   // i in [0, N*16)
    if (i >= n8) return;
    float4 a = feat[2 * i];
    float4 b = feat[2 * i + 1];
    __half2 h0 = __floats2half2_rn(a.x, a.y);
    __half2 h1 = __floats2half2_rn(a.z, a.w);
    __half2 h2 = __floats2half2_rn(b.x, b.y);
    __half2 h3 = __floats2half2_rn(b.z, b.w);
    uint4 v;
    v.x = *reinterpret_cast<unsigned int*>(&h0);
    v.y = *reinterpret_cast<unsigned int*>(&h1);
    v.z = *reinterpret_cast<unsigned int*>(&h2);
    v.w = *reinterpret_cast<unsigned int*>(&h3);
    g_featH[i] = v;
}

static __device__ __forceinline__ __half2 u2h(unsigned int x)
{
    return *reinterpret_cast<const __half2*>(&x);
}

// One full warp per edge, 8 edges ILP. Each lane loads 4B (one half2) from
// each 128B half-row chunk: every LDG.32 = exactly one L1 line = 1 wavefront.
__global__ void __launch_bounds__(256) batch_dot_w8_kernel(
    const int4* __restrict__ edges2,   // edge pairs: (s,d,s,d)
    float4* __restrict__ out4,         // output quads
    int n_warps)                       // = n_edges/8
{
    int gtid = blockIdx.x * blockDim.x + threadIdx.x;
    int w    = gtid >> 5;              // warp index = 8-edge chunk
    int lane = gtid & 31;
    if (w >= n_warps) return;

    const unsigned int* __restrict__ ft =
        reinterpret_cast<const unsigned int*>(g_featH);

    int4 ea = edges2[4 * w];
    int4 eb = edges2[4 * w + 1];
    int4 ec = edges2[4 * w + 2];
    int4 ed = edges2[4 * w + 3];

    int src[8] = {ea.x, ea.z, eb.x, eb.z, ec.x, ec.z, ed.x, ed.z};
    int dst[8] = {ea.y, ea.w, eb.y, eb.w, ec.y, ec.w, ed.y, ed.w};

    unsigned int a0[8], a1[8], b0[8], b1[8];
    #pragma unroll
    for (int i = 0; i < 8; i++) {
        const unsigned int* rs = ft + (size_t)src[i] * 64;   // 64 u32 per row
        const unsigned int* rd = ft + (size_t)dst[i] * 64;
        a0[i] = __ldg(rs + lane);        // chunk0: line 0 of row
        a1[i] = __ldg(rs + 32 + lane);   // chunk1: line 1 of row
        b0[i] = __ldg(rd + lane);
        b1[i] = __ldg(rd + 32 + lane);
    }

    float s[8];
    #pragma unroll
    for (int i = 0; i < 8; i++) {
        __half2 p = __hmul2(u2h(a0[i]), u2h(b0[i]));
        p = __hfma2(u2h(a1[i]), u2h(b1[i]), p);   // 2-product fp16 chains
        float2 f = __half22float2(p);
        s[i] = f.x + f.y;
    }

    // 5-step butterfly over 32 lanes, interleaved across 8 edges
    #pragma unroll
    for (int off = 16; off > 0; off >>= 1) {
        #pragma unroll
        for (int i = 0; i < 8; i++)
            s[i] += __shfl_xor_sync(0xffffffffu, s[i], off);
    }

    if (lane == 0) {
        out4[2 * w]     = make_float4(s[0], s[1], s[2], s[3]);
        out4[2 * w + 1] = make_float4(s[4], s[5], s[6], s[7]);
    }
}

static __device__ __forceinline__ float dot8(uint4 sa, uint4 sb)
{
    const __half2* ha = reinterpret_cast<const __half2*>(&sa);
    const __half2* hb = reinterpret_cast<const __half2*>(&sb);
    __half2 cA = __hmul2(ha[0], hb[0]);
    __half2 cB = __hmul2(ha[1], hb[1]);
    cA = __hfma2(ha[2], hb[2], cA);
    cB = __hfma2(ha[3], hb[3], cB);
    float2 fA = __half22float2(cA);
    float2 fB = __half22float2(cB);
    return (fA.x + fA.y) + (fB.x + fB.y);
}

// Tail: one 16-lane group per remaining edge (n_edges % 8 edges).
__global__ void batch_dot_tail_kernel(
    const int2* __restrict__ edges, float* __restrict__ out,
    int e_start, int n_edges)
{
    int e    = e_start + (threadIdx.x >> 4);
    int lane = threadIdx.x & 15;
    if (e >= n_edges) return;
    int2 ed = edges[e];
    uint4 sa = __ldg(&g_featH[(size_t)ed.x * 16 + lane]);
    uint4 sb = __ldg(&g_featH[(size_t)ed.y * 16 + lane]);
    float s = dot8(sa, sb);
    #pragma unroll
    for (int off = 8; off > 0; off >>= 1)
        s += __shfl_xor_sync(0xffffffffu, s, off);
    if (lane == 0) out[e] = s;
}

extern "C" void kernel_launch(void* const* d_in, const int* in_sizes, int n_in,
                              void* d_out, int out_size)
{
    const int2* edges = (const int2*)d_in[0];
    const float4* feat = (const float4*)d_in[1];
    float* out = (float*)d_out;

    int n_edges = in_sizes[0] / 2;
    int n_nodes = in_sizes[1] / 128;
    int n8      = n_nodes * 16;

    convert_k<<<(n8 + 255) / 256, 256>>>(feat, n8);

    int n_warps = n_edges / 8;                 // one warp per 8 edges
    long long total_threads = (long long)n_warps * 32;
    int blocks = (int)((total_threads + 255) / 256);
    if (blocks > 0)
        batch_dot_w8_kernel<<<blocks, 256>>>((const int4*)edges, (float4*)out, n_warps);

    int tail = n_edges - n_warps * 8;
    if (tail > 0)
        batch_dot_tail_kernel<<<1, 16 * tail>>>(edges, out, n_warps * 8, n_edges);
}

// round 17
// speedup vs baseline: 1.1726x; 1.1726x over previous
#include <cuda_runtime.h>
#include <cuda_fp16.h>

// BatchDotPred: out[e] = dot(feat[src[e]], feat[dst[e]]), D=128.
//
// R13 (16-lane groups, LDG.128, 8-edge ILP) = 70.1us; dot kernel 62us with
// L1=78%, nothing saturated -> latency under-coverage. ptxas held only 40
// regs => MLP_eff ~7, not the 16 written.
// R14 (single-line LDG.32) falsified: big LDGs are cheaper per line.
// R15: 16 edges per group + __launch_bounds__(256,2) (128-reg budget) to
// force ~24-32 gathers in flight per lane; occ ~16 warps/SM is enough once
// per-warp MLP is deep (16x24=384 lines in flight > ~250 needed).

#define N_NODES_MAX 100000

// fp16 feature table: 100000 rows x 128 halves = 256B/row, as uint4 (8 halves).
__device__ uint4 g_featH[N_NODES_MAX * 16];

__global__ void __launch_bounds__(256) convert_k(const float4* __restrict__ feat, int n8)
{
    int i = blockIdx.x * blockDim.x + threadIdx.x;   // i in [0, N*16)
    if (i >= n8) return;
    float4 a = feat[2 * i];
    float4 b = feat[2 * i + 1];
    __half2 h0 = __floats2half2_rn(a.x, a.y);
    __half2 h1 = __floats2half2_rn(a.z, a.w);
    __half2 h2 = __floats2half2_rn(b.x, b.y);
    __half2 h3 = __floats2half2_rn(b.z, b.w);
    uint4 v;
    v.x = *reinterpret_cast<unsigned int*>(&h0);
    v.y = *reinterpret_cast<unsigned int*>(&h1);
    v.z = *reinterpret_cast<unsigned int*>(&h2);
    v.w = *reinterpret_cast<unsigned int*>(&h3);
    g_featH[i] = v;
}

static __device__ __forceinline__ float dot8(uint4 sa, uint4 sb)
{
    const __half2* ha = reinterpret_cast<const __half2*>(&sa);
    const __half2* hb = reinterpret_cast<const __half2*>(&sb);
    __half2 cA = __hmul2(ha[0], hb[0]);
    __half2 cB = __hmul2(ha[1], hb[1]);
    cA = __hfma2(ha[2], hb[2], cA);
    cB = __hfma2(ha[3], hb[3], cB);
    float2 fA = __half22float2(cA);
    float2 fB = __half22float2(cB);
    return (fA.x + fA.y) + (fB.x + fB.y);
}

// One 16-lane group handles SIXTEEN consecutive edges (32 gathers in flight).
__global__ void __launch_bounds__(256, 2) batch_dot_h16_kernel(
    const int4* __restrict__ edges2,   // edge pairs: (s,d,s,d)
    float4* __restrict__ out4,         // output quads
    int n_groups)                      // = n_edges/16
{
    int gtid = blockIdx.x * blockDim.x + threadIdx.x;
    int g    = gtid >> 4;              // group index = 16-edge chunk
    int lane = gtid & 15;
    if (g >= n_groups) return;

    int4 e[8];
    #pragma unroll
    for (int i = 0; i < 8; i++)
        e[i] = edges2[8 * g + i];      // 16 edges

    // issue all 32 gathers before any math
    uint4 sa[16], sb[16];
    #pragma unroll
    for (int i = 0; i < 8; i++) {
        sa[2 * i]     = __ldg(&g_featH[(size_t)e[i].x * 16 + lane]);
        sb[2 * i]     = __ldg(&g_featH[(size_t)e[i].y * 16 + lane]);
        sa[2 * i + 1] = __ldg(&g_featH[(size_t)e[i].z * 16 + lane]);
        sb[2 * i + 1] = __ldg(&g_featH[(size_t)e[i].w * 16 + lane]);
    }

    float s[16];
    #pragma unroll
    for (int i = 0; i < 16; i++)
        s[i] = dot8(sa[i], sb[i]);

    // 4-stage butterfly across the 16-lane group, interleaved over 16 edges
    #pragma unroll
    for (int off = 8; off > 0; off >>= 1) {
        #pragma unroll
        for (int i = 0; i < 16; i++)
            s[i] += __shfl_xor_sync(0xffffffffu, s[i], off);
    }

    if (lane == 0) {
        #pragma unroll
        for (int q = 0; q < 4; q++)
            out4[4 * g + q] = make_float4(s[4 * q], s[4 * q + 1],
                                          s[4 * q + 2], s[4 * q + 3]);
    }
}

// Tail: one 16-lane group per remaining edge (n_edges % 16 edges).
__global__ void batch_dot_tail_kernel(
    const int2* __restrict__ edges, float* __restrict__ out,
    int e_start, int n_edges)
{
    int e    = e_start + (threadIdx.x >> 4);
    int lane = threadIdx.x & 15;
    if (e >= n_edges) return;
    int2 ed = edges[e];
    uint4 sa = __ldg(&g_featH[(size_t)ed.x * 16 + lane]);
    uint4 sb = __ldg(&g_featH[(size_t)ed.y * 16 + lane]);
    float s = dot8(sa, sb);
    #pragma unroll
    for (int off = 8; off > 0; off >>= 1)
        s += __shfl_xor_sync(0xffffffffu, s, off);
    if (lane == 0) out[e] = s;
}

extern "C" void kernel_launch(void* const* d_in, const int* in_sizes, int n_in,
                              void* d_out, int out_size)
{
    const int2* edges = (const int2*)d_in[0];
    const float4* feat = (const float4*)d_in[1];
    float* out = (float*)d_out;

    int n_edges = in_sizes[0] / 2;
    int n_nodes = in_sizes[1] / 128;
    int n8      = n_nodes * 16;

    convert_k<<<(n8 + 255) / 256, 256>>>(feat, n8);

    int n_groups = n_edges / 16;
    long long total_threads = (long long)n_groups * 16;
    int blocks = (int)((total_threads + 255) / 256);
    if (blocks > 0)
        batch_dot_h16_kernel<<<blocks, 256>>>((const int4*)edges, (float4*)out, n_groups);

    int tail = n_edges - n_groups * 16;
    if (tail > 0)
        batch_dot_tail_kernel<<<1, 16 * tail>>>(edges, out, n_groups * 16, n_edges);
}